// round 1
// baseline (speedup 1.0000x reference)
#include <cuda_runtime.h>
#include <math.h>

#define BB 32
#define HH 256
#define LL 2048
#define NS 64
#define FF 32
#define BHL (BB*HH*LL)

// ---------------- scratch (device globals; no runtime allocation) ----------------
__device__ float g_tb[BB*HH];
__device__ float g_wr[HH*NS], g_wi[HH*NS];
__device__ float g_c0r[HH*NS], g_c0i[HH*NS], g_c1r[HH*NS], g_c1i[HH*NS];
__device__ float g_z [BHL];   // LayerNorm output z; later reused to hold gated activations
__device__ float g_yf[BHL];   // forward scan output; later reused to hold gelu(y)
__device__ float g_yb[BHL];   // backward scan output

// ---------------- t @ Wt^T + bt ----------------
__global__ void k_tb(const float* __restrict__ t, const float* __restrict__ Wt,
                     const float* __restrict__ bt)
{
    __shared__ float ts[HH];
    int b = blockIdx.x, h = threadIdx.x;
    ts[h] = t[b*HH + h];
    __syncthreads();
    float acc = bt[h];
    const float* wrow = Wt + (size_t)h*HH;
    #pragma unroll 8
    for (int k = 0; k < HH; k++) acc = fmaf(ts[k], wrow[k], acc);
    g_tb[b*HH + h] = acc;
}

// ---------------- SSM parameter prep: w = exp(dt*A), Cd = 2*(C)*(w-1)/A ----------------
__global__ void k_ssm(const float* __restrict__ log_dt, const float* __restrict__ logA_real,
                      const float* __restrict__ A_imag, const float* __restrict__ C_re,
                      const float* __restrict__ C_im)
{
    int i = blockIdx.x*blockDim.x + threadIdx.x;
    if (i >= HH*NS) return;
    int h = i / NS;
    float dt = expf(log_dt[h]);
    float Ar = -expf(logA_real[i]);
    float Ai = A_imag[i];
    float dr = dt*Ar, di = dt*Ai;
    float er = expf(dr);
    float wr = er*cosf(di), wi = er*sinf(di);
    g_wr[i] = wr; g_wi[i] = wi;
    float Er = wr - 1.0f, Ei = wi;                 // exp(dtA) - 1
    float inv = 1.0f/(Ar*Ar + Ai*Ai);
    float qr = (Er*Ar + Ei*Ai)*inv;                // E / A
    float qi = (Ei*Ar - Er*Ai)*inv;
    {
        float cr = C_re[i], ci = C_im[i];
        g_c0r[i] = 2.0f*(cr*qr - ci*qi);
        g_c0i[i] = 2.0f*(cr*qi + ci*qr);
    }
    {
        float cr = C_re[HH*NS + i], ci = C_im[HH*NS + i];
        g_c1r[i] = 2.0f*(cr*qr - ci*qi);
        g_c1i[i] = 2.0f*(cr*qi + ci*qr);
    }
}

// ---------------- xin = x + tb ; LayerNorm over H -> z ----------------
__global__ void k_ln(const float* __restrict__ x, const float* __restrict__ ln_g,
                     const float* __restrict__ ln_b)
{
    __shared__ float tbs[HH], gs[HH], bs[HH];
    int b = blockIdx.y;
    int l = blockIdx.x*256 + threadIdx.x;
    tbs[threadIdx.x] = g_tb[b*HH + threadIdx.x];
    gs[threadIdx.x]  = ln_g[threadIdx.x];
    bs[threadIdx.x]  = ln_b[threadIdx.x];
    __syncthreads();
    const float* xb = x + (size_t)b*HH*LL + l;
    float s = 0.f, ss = 0.f;
    #pragma unroll 8
    for (int h = 0; h < HH; h++) {
        float v = xb[(size_t)h*LL] + tbs[h];
        s += v; ss = fmaf(v, v, ss);
    }
    float mu  = s * (1.0f/HH);
    float var = ss*(1.0f/HH) - mu*mu;
    float rstd = rsqrtf(var + 1e-5f);
    float* zb = g_z + (size_t)b*HH*LL + l;
    #pragma unroll 8
    for (int h = 0; h < HH; h++) {
        float v = xb[(size_t)h*LL] + tbs[h];
        zb[(size_t)h*LL] = (v - mu)*rstd*gs[h] + bs[h];
    }
}

// ---------------- bidirectional diagonal-SSM scan: one warp per (b,h,dir) ----------------
__global__ void k_scan()
{
    __shared__ float sm[8][32*33];
    int wid  = threadIdx.x >> 5;
    int lane = threadIdx.x & 31;
    int gw   = blockIdx.x*8 + wid;       // 0 .. 2*B*H-1
    int bh   = gw >> 1;
    int dir  = gw & 1;
    int h    = bh & (HH-1);
    int ci   = h*NS + lane;

    float w0r = g_wr[ci],    w0i = g_wi[ci];
    float w1r = g_wr[ci+32], w1i = g_wi[ci+32];
    float c0r, c0i, c1r, c1i;
    if (dir == 0) { c0r = g_c0r[ci]; c0i = g_c0i[ci]; c1r = g_c0r[ci+32]; c1i = g_c0i[ci+32]; }
    else          { c0r = g_c1r[ci]; c0i = g_c1i[ci]; c1r = g_c1r[ci+32]; c1i = g_c1i[ci+32]; }

    const float* zp = g_z + (size_t)bh*LL;
    float* yp = (dir == 0 ? g_yf : g_yb) + (size_t)bh*LL;
    float* smw = sm[wid];

    float s0r = 0.f, s0i = 0.f, s1r = 0.f, s1i = 0.f;

    if (dir == 0) {
        for (int t = 0; t < LL/32; t++) {
            int l0 = t*32;
            float zv = zp[l0 + lane];
            #pragma unroll
            for (int j = 0; j < 32; j++) {
                float zl = __shfl_sync(0xffffffffu, zv, j);
                float n0r = fmaf(w0r, s0r, fmaf(-w0i, s0i, zl));
                float n0i = fmaf(w0r, s0i, w0i*s0r);
                float n1r = fmaf(w1r, s1r, fmaf(-w1i, s1i, zl));
                float n1i = fmaf(w1r, s1i, w1i*s1r);
                s0r = n0r; s0i = n0i; s1r = n1r; s1i = n1i;
                float p = fmaf(c0r, s0r, fmaf(-c0i, s0i, fmaf(c1r, s1r, -(c1i*s1i))));
                smw[j*33 + lane] = p;
            }
            __syncwarp();
            float acc = 0.f;
            #pragma unroll
            for (int k = 0; k < 32; k++) acc += smw[lane*33 + k];
            yp[l0 + lane] = acc;
            __syncwarp();
        }
    } else {
        for (int t = 0; t < LL/32; t++) {
            int l0 = LL - 32*(t+1);
            float zv = zp[l0 + lane];
            #pragma unroll
            for (int j = 31; j >= 0; j--) {
                // emit y_b[l0+j] from state BEFORE absorbing z[l0+j]
                float p = fmaf(c0r, s0r, fmaf(-c0i, s0i, fmaf(c1r, s1r, -(c1i*s1i))));
                smw[j*33 + lane] = p;
                float zl = __shfl_sync(0xffffffffu, zv, j);
                float n0r = fmaf(w0r, s0r, fmaf(-w0i, s0i, zl));
                float n0i = fmaf(w0r, s0i, w0i*s0r);
                float n1r = fmaf(w1r, s1r, fmaf(-w1i, s1i, zl));
                float n1i = fmaf(w1r, s1i, w1i*s1r);
                s0r = n0r; s0i = n0i; s1r = n1r; s1i = n1i;
            }
            __syncwarp();
            float acc = 0.f;
            #pragma unroll
            for (int k = 0; k < 32; k++) acc += smw[lane*33 + k];
            yp[l0 + lane] = acc;
            __syncwarp();
        }
    }
}

// ---------------- y = gelu(yf + yb + D*z)  (tanh approximation, matches jax default) ----------------
__global__ void k_gelu(const float* __restrict__ Dv)
{
    int i = blockIdx.x*256 + threadIdx.x;
    int h = (i >> 11) & (HH-1);
    float y = g_yf[i] + g_yb[i] + Dv[h]*g_z[i];
    float u = 0.7978845608028654f * fmaf(0.044715f*y, y*y, y);
    g_yf[i] = 0.5f*y*(1.0f + tanhf(u));
}

// ---------------- stage1: Wout GEMM + feature GEMM + residual + gate -> g_z ----------------
__global__ void k_stage1(const float* __restrict__ Wout, const float* __restrict__ bout,
                         const float* __restrict__ x, const float* __restrict__ feat,
                         const float* __restrict__ Wf, const float* __restrict__ bf)
{
    __shared__ float As[64][17];
    __shared__ float Bs[16][64];
    const int b  = blockIdx.z;
    const int g0 = blockIdx.y * 64;
    const int l0 = blockIdx.x * 64;
    const int tid = threadIdx.x;
    const int tx = tid & 15, ty = tid >> 4;
    const int wrow = tid >> 2, wkg = (tid & 3) * 4;
    const int brow = tid >> 4, bcg = (tid & 15) * 4;

    float acc[4][4];
    #pragma unroll
    for (int i = 0; i < 4; i++)
        #pragma unroll
        for (int j = 0; j < 4; j++) acc[i][j] = 0.f;

    const float* act = g_yf + (size_t)b*HH*LL;
    for (int k0 = 0; k0 < HH; k0 += 16) {
        float4 w4 = *(const float4*)(Wout + (size_t)(g0+wrow)*HH + k0 + wkg);
        As[wrow][wkg+0] = w4.x; As[wrow][wkg+1] = w4.y;
        As[wrow][wkg+2] = w4.z; As[wrow][wkg+3] = w4.w;
        *(float4*)&Bs[brow][bcg] = *(const float4*)(act + (size_t)(k0+brow)*LL + l0 + bcg);
        __syncthreads();
        #pragma unroll
        for (int k = 0; k < 16; k++) {
            float4 bv = *(const float4*)&Bs[k][tx*4];
            #pragma unroll
            for (int i = 0; i < 4; i++) {
                float a = As[ty*4+i][k];
                acc[i][0] = fmaf(a, bv.x, acc[i][0]);
                acc[i][1] = fmaf(a, bv.y, acc[i][1]);
                acc[i][2] = fmaf(a, bv.z, acc[i][2]);
                acc[i][3] = fmaf(a, bv.w, acc[i][3]);
            }
        }
        __syncthreads();
    }
    const float* fb = feat + (size_t)b*FF*LL;
    for (int k0 = 0; k0 < FF; k0 += 16) {
        float4 w4 = *(const float4*)(Wf + (size_t)(g0+wrow)*FF + k0 + wkg);
        As[wrow][wkg+0] = w4.x; As[wrow][wkg+1] = w4.y;
        As[wrow][wkg+2] = w4.z; As[wrow][wkg+3] = w4.w;
        *(float4*)&Bs[brow][bcg] = *(const float4*)(fb + (size_t)(k0+brow)*LL + l0 + bcg);
        __syncthreads();
        #pragma unroll
        for (int k = 0; k < 16; k++) {
            float4 bv = *(const float4*)&Bs[k][tx*4];
            #pragma unroll
            for (int i = 0; i < 4; i++) {
                float a = As[ty*4+i][k];
                acc[i][0] = fmaf(a, bv.x, acc[i][0]);
                acc[i][1] = fmaf(a, bv.y, acc[i][1]);
                acc[i][2] = fmaf(a, bv.z, acc[i][2]);
                acc[i][3] = fmaf(a, bv.w, acc[i][3]);
            }
        }
        __syncthreads();
    }
    #pragma unroll
    for (int i = 0; i < 4; i++) {
        int g = g0 + ty*4 + i;
        float base = bout[g] + bf[g] + g_tb[b*HH + g];
        const float4 xv = *(const float4*)(x + ((size_t)b*HH + g)*LL + l0 + tx*4);
        float o0 = acc[i][0] + base + xv.x;
        float o1 = acc[i][1] + base + xv.y;
        float o2 = acc[i][2] + base + xv.z;
        float o3 = acc[i][3] + base + xv.w;
        float4 gv;
        gv.x = tanhf(o0) / (1.f + expf(-o0));
        gv.y = tanhf(o1) / (1.f + expf(-o1));
        gv.z = tanhf(o2) / (1.f + expf(-o2));
        gv.w = tanhf(o3) / (1.f + expf(-o3));
        *(float4*)(g_z + ((size_t)b*HH + g)*LL + l0 + tx*4) = gv;
    }
}

// ---------------- stage2: o1 = W1@g + b1 + x ; o2 = W2@g + b2 ----------------
__global__ void k_stage2(const float* __restrict__ W1, const float* __restrict__ b1,
                         const float* __restrict__ W2, const float* __restrict__ b2,
                         const float* __restrict__ x, float* __restrict__ o1,
                         float* __restrict__ o2)
{
    __shared__ float A1[64][17];
    __shared__ float A2[64][17];
    __shared__ float Bs[16][64];
    const int b  = blockIdx.z;
    const int g0 = blockIdx.y * 64;
    const int l0 = blockIdx.x * 64;
    const int tid = threadIdx.x;
    const int tx = tid & 15, ty = tid >> 4;
    const int wrow = tid >> 2, wkg = (tid & 3) * 4;
    const int brow = tid >> 4, bcg = (tid & 15) * 4;

    float acc1[4][4], acc2[4][4];
    #pragma unroll
    for (int i = 0; i < 4; i++)
        #pragma unroll
        for (int j = 0; j < 4; j++) { acc1[i][j] = 0.f; acc2[i][j] = 0.f; }

    const float* gb = g_z + (size_t)b*HH*LL;
    for (int k0 = 0; k0 < HH; k0 += 16) {
        float4 w4 = *(const float4*)(W1 + (size_t)(g0+wrow)*HH + k0 + wkg);
        A1[wrow][wkg+0] = w4.x; A1[wrow][wkg+1] = w4.y;
        A1[wrow][wkg+2] = w4.z; A1[wrow][wkg+3] = w4.w;
        float4 v4 = *(const float4*)(W2 + (size_t)(g0+wrow)*HH + k0 + wkg);
        A2[wrow][wkg+0] = v4.x; A2[wrow][wkg+1] = v4.y;
        A2[wrow][wkg+2] = v4.z; A2[wrow][wkg+3] = v4.w;
        *(float4*)&Bs[brow][bcg] = *(const float4*)(gb + (size_t)(k0+brow)*LL + l0 + bcg);
        __syncthreads();
        #pragma unroll
        for (int k = 0; k < 16; k++) {
            float4 bv = *(const float4*)&Bs[k][tx*4];
            #pragma unroll
            for (int i = 0; i < 4; i++) {
                float a = A1[ty*4+i][k];
                acc1[i][0] = fmaf(a, bv.x, acc1[i][0]);
                acc1[i][1] = fmaf(a, bv.y, acc1[i][1]);
                acc1[i][2] = fmaf(a, bv.z, acc1[i][2]);
                acc1[i][3] = fmaf(a, bv.w, acc1[i][3]);
                float c = A2[ty*4+i][k];
                acc2[i][0] = fmaf(c, bv.x, acc2[i][0]);
                acc2[i][1] = fmaf(c, bv.y, acc2[i][1]);
                acc2[i][2] = fmaf(c, bv.z, acc2[i][2]);
                acc2[i][3] = fmaf(c, bv.w, acc2[i][3]);
            }
        }
        __syncthreads();
    }
    #pragma unroll
    for (int i = 0; i < 4; i++) {
        int g = g0 + ty*4 + i;
        size_t off = ((size_t)b*HH + g)*LL + l0 + tx*4;
        const float4 xv = *(const float4*)(x + off);
        float bb1 = b1[g], bb2 = b2[g];
        float4 r1, r2;
        r1.x = acc1[i][0] + bb1 + xv.x;
        r1.y = acc1[i][1] + bb1 + xv.y;
        r1.z = acc1[i][2] + bb1 + xv.z;
        r1.w = acc1[i][3] + bb1 + xv.w;
        r2.x = acc2[i][0] + bb2;
        r2.y = acc2[i][1] + bb2;
        r2.z = acc2[i][2] + bb2;
        r2.w = acc2[i][3] + bb2;
        *(float4*)(o1 + off) = r1;
        *(float4*)(o2 + off) = r2;
    }
}

// ---------------- launch ----------------
extern "C" void kernel_launch(void* const* d_in, const int* in_sizes, int n_in,
                              void* d_out, int out_size)
{
    const float* x        = (const float*)d_in[0];
    const float* t        = (const float*)d_in[1];
    const float* feat     = (const float*)d_in[2];
    const float* Wt       = (const float*)d_in[3];
    const float* bt       = (const float*)d_in[4];
    const float* ln_g     = (const float*)d_in[5];
    const float* ln_b     = (const float*)d_in[6];
    const float* log_dt   = (const float*)d_in[7];
    const float* logA_real= (const float*)d_in[8];
    const float* A_imag   = (const float*)d_in[9];
    const float* C_re     = (const float*)d_in[10];
    const float* C_im     = (const float*)d_in[11];
    const float* Dv       = (const float*)d_in[12];
    const float* Wout     = (const float*)d_in[13];
    const float* bout     = (const float*)d_in[14];
    const float* W1       = (const float*)d_in[15];
    const float* b1       = (const float*)d_in[16];
    const float* W2       = (const float*)d_in[17];
    const float* b2       = (const float*)d_in[18];
    const float* Wf       = (const float*)d_in[19];
    const float* bf       = (const float*)d_in[20];

    float* o1 = (float*)d_out;
    float* o2 = (float*)d_out + (size_t)BHL;

    k_tb<<<BB, 256>>>(t, Wt, bt);
    k_ssm<<<(HH*NS+255)/256, 256>>>(log_dt, logA_real, A_imag, C_re, C_im);
    k_ln<<<dim3(LL/256, BB), 256>>>(x, ln_g, ln_b);
    k_scan<<<(2*BB*HH)/8, 256>>>();
    k_gelu<<<BHL/256, 256>>>(Dv);
    k_stage1<<<dim3(LL/64, HH/64, BB), 256>>>(Wout, bout, x, feat, Wf, bf);
    k_stage2<<<dim3(LL/64, HH/64, BB), 256>>>(W1, b1, W2, b2, x, o1, o2);
}

// round 2
// speedup vs baseline: 1.0178x; 1.0178x over previous
#include <cuda_runtime.h>
#include <math.h>

#define BB 32
#define HH 256
#define LL 2048
#define NS 64
#define FF 32
#define BHL (BB*HH*LL)

typedef unsigned long long u64;

// ---------------- f32x2 helpers (sm_103a packed fp32) ----------------
__device__ __forceinline__ u64 pk2(float lo, float hi) {
    u64 r; asm("mov.b64 %0, {%1, %2};" : "=l"(r) : "f"(lo), "f"(hi)); return r;
}
__device__ __forceinline__ void up2(u64 v, float& a, float& b) {
    asm("mov.b64 {%0, %1}, %2;" : "=f"(a), "=f"(b) : "l"(v));
}
__device__ __forceinline__ u64 fma2(u64 a, u64 b, u64 c) {
    u64 d; asm("fma.rn.f32x2 %0, %1, %2, %3;" : "=l"(d) : "l"(a), "l"(b), "l"(c)); return d;
}
__device__ __forceinline__ u64 mul2(u64 a, u64 b) {
    u64 d; asm("mul.rn.f32x2 %0, %1, %2;" : "=l"(d) : "l"(a), "l"(b)); return d;
}
__device__ __forceinline__ u64 add2(u64 a, u64 b) {
    u64 d; asm("add.rn.f32x2 %0, %1, %2;" : "=l"(d) : "l"(a), "l"(b)); return d;
}

// gate = tanh(o)*sigmoid(o), via one __expf. Clamp keeps u^2*(u) finite.
__device__ __forceinline__ float gatef(float o) {
    float u = __expf(fminf(-o, 25.f));
    float u2 = u * u;
    return (1.f - u2) / ((1.f + u2) * (1.f + u));
}

// ---------------- scratch (device globals) ----------------
__device__ float g_tb[BB*HH];
__device__ float g_wr[HH*NS], g_wi[HH*NS];
__device__ float g_c0r[HH*NS], g_c0i[HH*NS], g_c1r[HH*NS], g_c1i[HH*NS];
__device__ float g_z [BHL];   // LayerNorm output z; later holds gated activations
__device__ float g_yf[BHL];   // fwd scan output -> gelu(y) in place

// ---------------- t @ Wt^T + bt ----------------
__global__ void k_tb(const float* __restrict__ t, const float* __restrict__ Wt,
                     const float* __restrict__ bt)
{
    __shared__ float ts[HH];
    int b = blockIdx.x, h = threadIdx.x;
    ts[h] = t[b*HH + h];
    __syncthreads();
    float acc = bt[h];
    const float* wrow = Wt + (size_t)h*HH;
    #pragma unroll 8
    for (int k = 0; k < HH; k++) acc = fmaf(ts[k], wrow[k], acc);
    g_tb[b*HH + h] = acc;
}

// ---------------- SSM parameter prep ----------------
__global__ void k_ssm(const float* __restrict__ log_dt, const float* __restrict__ logA_real,
                      const float* __restrict__ A_imag, const float* __restrict__ C_re,
                      const float* __restrict__ C_im)
{
    int i = blockIdx.x*blockDim.x + threadIdx.x;
    if (i >= HH*NS) return;
    int h = i / NS;
    float dt = expf(log_dt[h]);
    float Ar = -expf(logA_real[i]);
    float Ai = A_imag[i];
    float dr = dt*Ar, di = dt*Ai;
    float er = expf(dr);
    float wr = er*cosf(di), wi = er*sinf(di);
    g_wr[i] = wr; g_wi[i] = wi;
    float Er = wr - 1.0f, Ei = wi;
    float inv = 1.0f/(Ar*Ar + Ai*Ai);
    float qr = (Er*Ar + Ei*Ai)*inv;
    float qi = (Ei*Ar - Er*Ai)*inv;
    {
        float cr = C_re[i], ci = C_im[i];
        g_c0r[i] = 2.0f*(cr*qr - ci*qi);
        g_c0i[i] = 2.0f*(cr*qi + ci*qr);
    }
    {
        float cr = C_re[HH*NS + i], ci = C_im[HH*NS + i];
        g_c1r[i] = 2.0f*(cr*qr - ci*qi);
        g_c1i[i] = 2.0f*(cr*qi + ci*qr);
    }
}

// ---------------- xin = x + tb ; LayerNorm over H -> z ----------------
__global__ void k_ln(const float* __restrict__ x, const float* __restrict__ ln_g,
                     const float* __restrict__ ln_b)
{
    __shared__ float tbs[HH], gs[HH], bs[HH];
    int b = blockIdx.y;
    int l = blockIdx.x*256 + threadIdx.x;
    tbs[threadIdx.x] = g_tb[b*HH + threadIdx.x];
    gs[threadIdx.x]  = ln_g[threadIdx.x];
    bs[threadIdx.x]  = ln_b[threadIdx.x];
    __syncthreads();
    const float* xb = x + (size_t)b*HH*LL + l;
    float s = 0.f, ss = 0.f;
    #pragma unroll 8
    for (int h = 0; h < HH; h++) {
        float v = xb[(size_t)h*LL] + tbs[h];
        s += v; ss = fmaf(v, v, ss);
    }
    float mu  = s * (1.0f/HH);
    float var = ss*(1.0f/HH) - mu*mu;
    float rstd = rsqrtf(var + 1e-5f);
    float* zb = g_z + (size_t)b*HH*LL + l;
    #pragma unroll 8
    for (int h = 0; h < HH; h++) {
        float v = xb[(size_t)h*LL] + tbs[h];
        zb[(size_t)h*LL] = (v - mu)*rstd*gs[h] + bs[h];
    }
}

// ---------------- bidirectional scan, f32x2, one warp per (b,h), fused gelu ----------------
#define SCAN_WPB 4
__global__ __launch_bounds__(32*SCAN_WPB) void k_scan(const float* __restrict__ Dv)
{
    __shared__ __align__(16) u64 pbuf[SCAN_WPB][32*33];
    __shared__ __align__(16) u64 zbuf[SCAN_WPB][32];
    int wid  = threadIdx.x >> 5;
    int lane = threadIdx.x & 31;
    int bh   = blockIdx.x*SCAN_WPB + wid;
    int h    = bh & (HH-1);
    int ci   = h*NS + lane;
    u64* pw = pbuf[wid];
    u64* zw = zbuf[wid];

    u64 wr2  = pk2(g_wr[ci],  g_wr[ci+32]);
    u64 wi2  = pk2(g_wi[ci],  g_wi[ci+32]);
    u64 wi2n = pk2(-g_wi[ci], -g_wi[ci+32]);
    const float* zp = g_z  + (size_t)bh*LL;
    float*       yp = g_yf + (size_t)bh*LL;

    // ---- phase 1: forward scan ----
    {
        u64 cr2  = pk2(g_c0r[ci],  g_c0r[ci+32]);
        u64 ci2n = pk2(-g_c0i[ci], -g_c0i[ci+32]);
        u64 sr = 0ULL, si = 0ULL;
        for (int t = 0; t < LL/32; t++) {
            int l0 = t*32;
            float zv = zp[l0 + lane];
            zw[lane] = pk2(zv, zv);
            __syncwarp();
            #pragma unroll
            for (int j = 0; j < 32; j++) {
                u64 z2  = zw[j];
                u64 nsr = fma2(wr2, sr, fma2(wi2n, si, z2));
                si = fma2(wr2, si, mul2(wi2, sr));
                sr = nsr;
                pw[j*33 + lane] = fma2(cr2, sr, mul2(ci2n, si));
            }
            __syncwarp();
            u64 acc = 0ULL;
            #pragma unroll
            for (int k = 0; k < 32; k++) acc = add2(acc, pw[lane*33 + k]);
            float a, b; up2(acc, a, b);
            yp[l0 + lane] = a + b;
            __syncwarp();
        }
    }
    // ---- phase 2: backward scan + D*z + gelu (fused epilogue) ----
    {
        u64 cr2  = pk2(g_c1r[ci],  g_c1r[ci+32]);
        u64 ci2n = pk2(-g_c1i[ci], -g_c1i[ci+32]);
        float d = Dv[h];
        u64 sr = 0ULL, si = 0ULL;
        for (int t = 0; t < LL/32; t++) {
            int l0 = LL - 32*(t+1);
            float zv = zp[l0 + lane];
            zw[lane] = pk2(zv, zv);
            __syncwarp();
            #pragma unroll
            for (int j = 31; j >= 0; j--) {
                // emit y_b contribution from state BEFORE absorbing z[l0+j]
                pw[j*33 + lane] = fma2(cr2, sr, mul2(ci2n, si));
                u64 z2  = zw[j];
                u64 nsr = fma2(wr2, sr, fma2(wi2n, si, z2));
                si = fma2(wr2, si, mul2(wi2, sr));
                sr = nsr;
            }
            __syncwarp();
            u64 acc = 0ULL;
            #pragma unroll
            for (int k = 0; k < 32; k++) acc = add2(acc, pw[lane*33 + k]);
            float a, b; up2(acc, a, b);
            float y = yp[l0 + lane] + a + b + d*zv;
            // gelu (tanh approximation, matches jax default)
            float u = 0.7978845608028654f * fmaf(0.044715f*y, y*y, y);
            float e = __expf(fminf(-2.f*u, 80.f));
            float th = (1.f - e) / (1.f + e);
            yp[l0 + lane] = 0.5f*y*(1.f + th);
            __syncwarp();
        }
    }
}

// ---------------- stage1: (Wout GEMM + feature GEMM + residual + gate) -> g_z ----------------
__global__ __launch_bounds__(256) void k_stage1(const float* __restrict__ Wout, const float* __restrict__ bout,
                         const float* __restrict__ x, const float* __restrict__ feat,
                         const float* __restrict__ Wf, const float* __restrict__ bf)
{
    __shared__ __align__(16) float Ws[16][130];
    __shared__ __align__(16) u64  Bs[16][65];
    const int b  = blockIdx.z;
    const int g0 = blockIdx.y * 128;
    const int l0 = blockIdx.x * 64;
    const int tid = threadIdx.x;
    const int tx = tid & 15, ty = tid >> 4;
    const int arow = tid >> 1, akg = (tid & 1) * 8;
    const int brow = tid >> 4, bc0 = tid & 15;

    u64 acc[4][4];
    #pragma unroll
    for (int r = 0; r < 4; r++)
        #pragma unroll
        for (int j = 0; j < 4; j++) acc[r][j] = 0ULL;

    const float* act = g_yf + (size_t)b*HH*LL;
    for (int k0 = 0; k0 < HH; k0 += 16) {
        float4 w0 = *(const float4*)(Wout + (size_t)(g0+arow)*HH + k0 + akg);
        float4 w1 = *(const float4*)(Wout + (size_t)(g0+arow)*HH + k0 + akg + 4);
        Ws[akg+0][arow]=w0.x; Ws[akg+1][arow]=w0.y; Ws[akg+2][arow]=w0.z; Ws[akg+3][arow]=w0.w;
        Ws[akg+4][arow]=w1.x; Ws[akg+5][arow]=w1.y; Ws[akg+6][arow]=w1.z; Ws[akg+7][arow]=w1.w;
        #pragma unroll
        for (int c = 0; c < 4; c++) {
            float v = act[(size_t)(k0+brow)*LL + l0 + bc0 + 16*c];
            Bs[brow][bc0 + 16*c] = pk2(v, v);
        }
        __syncthreads();
        #pragma unroll
        for (int k = 0; k < 16; k++) {
            u64 ap[4], bp[4];
            #pragma unroll
            for (int r = 0; r < 4; r++) ap[r] = *(const u64*)&Ws[k][ty*8 + 2*r];
            #pragma unroll
            for (int j = 0; j < 4; j++) bp[j] = Bs[k][16*j + tx];
            #pragma unroll
            for (int r = 0; r < 4; r++)
                #pragma unroll
                for (int j = 0; j < 4; j++)
                    acc[r][j] = fma2(ap[r], bp[j], acc[r][j]);
        }
        __syncthreads();
    }
    const float* fb = feat + (size_t)b*FF*LL;
    for (int k0 = 0; k0 < FF; k0 += 16) {
        float4 w0 = *(const float4*)(Wf + (size_t)(g0+arow)*FF + k0 + akg);
        float4 w1 = *(const float4*)(Wf + (size_t)(g0+arow)*FF + k0 + akg + 4);
        Ws[akg+0][arow]=w0.x; Ws[akg+1][arow]=w0.y; Ws[akg+2][arow]=w0.z; Ws[akg+3][arow]=w0.w;
        Ws[akg+4][arow]=w1.x; Ws[akg+5][arow]=w1.y; Ws[akg+6][arow]=w1.z; Ws[akg+7][arow]=w1.w;
        #pragma unroll
        for (int c = 0; c < 4; c++) {
            float v = fb[(size_t)(k0+brow)*LL + l0 + bc0 + 16*c];
            Bs[brow][bc0 + 16*c] = pk2(v, v);
        }
        __syncthreads();
        #pragma unroll
        for (int k = 0; k < 16; k++) {
            u64 ap[4], bp[4];
            #pragma unroll
            for (int r = 0; r < 4; r++) ap[r] = *(const u64*)&Ws[k][ty*8 + 2*r];
            #pragma unroll
            for (int j = 0; j < 4; j++) bp[j] = Bs[k][16*j + tx];
            #pragma unroll
            for (int r = 0; r < 4; r++)
                #pragma unroll
                for (int j = 0; j < 4; j++)
                    acc[r][j] = fma2(ap[r], bp[j], acc[r][j]);
        }
        __syncthreads();
    }
    float base[8];
    #pragma unroll
    for (int i = 0; i < 8; i++) {
        int g = g0 + ty*8 + i;
        base[i] = bout[g] + bf[g] + g_tb[b*HH + g];
    }
    #pragma unroll
    for (int r = 0; r < 4; r++) {
        int g = g0 + ty*8 + 2*r;
        #pragma unroll
        for (int j = 0; j < 4; j++) {
            float v0, v1; up2(acc[r][j], v0, v1);
            int col = l0 + 16*j + tx;
            size_t off0 = ((size_t)b*HH + g)*LL + col;
            size_t off1 = off0 + LL;
            float o0 = v0 + base[2*r]   + x[off0];
            float o1 = v1 + base[2*r+1] + x[off1];
            g_z[off0] = gatef(o0);
            g_z[off1] = gatef(o1);
        }
    }
}

// ---------------- stage2: o1 = W1@g + b1 + x ; o2 = W2@g + b2 ----------------
__global__ __launch_bounds__(256) void k_stage2(const float* __restrict__ W1, const float* __restrict__ b1,
                         const float* __restrict__ W2, const float* __restrict__ b2,
                         const float* __restrict__ x, float* __restrict__ o1,
                         float* __restrict__ o2)
{
    __shared__ __align__(16) float W1s[16][130];
    __shared__ __align__(16) float W2s[16][130];
    __shared__ __align__(16) u64  Bs[16][65];
    const int b  = blockIdx.z;
    const int g0 = blockIdx.y * 128;
    const int l0 = blockIdx.x * 64;
    const int tid = threadIdx.x;
    const int tx = tid & 15, ty = tid >> 4;
    const int arow = tid >> 1, akg = (tid & 1) * 8;
    const int brow = tid >> 4, bc0 = tid & 15;

    u64 acc1[4][4], acc2[4][4];
    #pragma unroll
    for (int r = 0; r < 4; r++)
        #pragma unroll
        for (int j = 0; j < 4; j++) { acc1[r][j] = 0ULL; acc2[r][j] = 0ULL; }

    const float* gb = g_z + (size_t)b*HH*LL;
    for (int k0 = 0; k0 < HH; k0 += 16) {
        float4 w0 = *(const float4*)(W1 + (size_t)(g0+arow)*HH + k0 + akg);
        float4 w1 = *(const float4*)(W1 + (size_t)(g0+arow)*HH + k0 + akg + 4);
        W1s[akg+0][arow]=w0.x; W1s[akg+1][arow]=w0.y; W1s[akg+2][arow]=w0.z; W1s[akg+3][arow]=w0.w;
        W1s[akg+4][arow]=w1.x; W1s[akg+5][arow]=w1.y; W1s[akg+6][arow]=w1.z; W1s[akg+7][arow]=w1.w;
        float4 v0 = *(const float4*)(W2 + (size_t)(g0+arow)*HH + k0 + akg);
        float4 v1 = *(const float4*)(W2 + (size_t)(g0+arow)*HH + k0 + akg + 4);
        W2s[akg+0][arow]=v0.x; W2s[akg+1][arow]=v0.y; W2s[akg+2][arow]=v0.z; W2s[akg+3][arow]=v0.w;
        W2s[akg+4][arow]=v1.x; W2s[akg+5][arow]=v1.y; W2s[akg+6][arow]=v1.z; W2s[akg+7][arow]=v1.w;
        #pragma unroll
        for (int c = 0; c < 4; c++) {
            float v = gb[(size_t)(k0+brow)*LL + l0 + bc0 + 16*c];
            Bs[brow][bc0 + 16*c] = pk2(v, v);
        }
        __syncthreads();
        #pragma unroll
        for (int k = 0; k < 16; k++) {
            u64 a1[4], a2[4], bp[4];
            #pragma unroll
            for (int r = 0; r < 4; r++) a1[r] = *(const u64*)&W1s[k][ty*8 + 2*r];
            #pragma unroll
            for (int r = 0; r < 4; r++) a2[r] = *(const u64*)&W2s[k][ty*8 + 2*r];
            #pragma unroll
            for (int j = 0; j < 4; j++) bp[j] = Bs[k][16*j + tx];
            #pragma unroll
            for (int r = 0; r < 4; r++)
                #pragma unroll
                for (int j = 0; j < 4; j++) {
                    acc1[r][j] = fma2(a1[r], bp[j], acc1[r][j]);
                    acc2[r][j] = fma2(a2[r], bp[j], acc2[r][j]);
                }
        }
        __syncthreads();
    }
    #pragma unroll
    for (int r = 0; r < 4; r++) {
        int g = g0 + ty*8 + 2*r;
        float bb1a = b1[g], bb1b = b1[g+1];
        float bb2a = b2[g], bb2b = b2[g+1];
        #pragma unroll
        for (int j = 0; j < 4; j++) {
            int col = l0 + 16*j + tx;
            size_t off0 = ((size_t)b*HH + g)*LL + col;
            size_t off1 = off0 + LL;
            float p0, p1, q0, q1;
            up2(acc1[r][j], p0, p1);
            up2(acc2[r][j], q0, q1);
            o1[off0] = p0 + bb1a + x[off0];
            o1[off1] = p1 + bb1b + x[off1];
            o2[off0] = q0 + bb2a;
            o2[off1] = q1 + bb2b;
        }
    }
}

// ---------------- launch ----------------
extern "C" void kernel_launch(void* const* d_in, const int* in_sizes, int n_in,
                              void* d_out, int out_size)
{
    const float* x        = (const float*)d_in[0];
    const float* t        = (const float*)d_in[1];
    const float* feat     = (const float*)d_in[2];
    const float* Wt       = (const float*)d_in[3];
    const float* bt       = (const float*)d_in[4];
    const float* ln_g     = (const float*)d_in[5];
    const float* ln_b     = (const float*)d_in[6];
    const float* log_dt   = (const float*)d_in[7];
    const float* logA_real= (const float*)d_in[8];
    const float* A_imag   = (const float*)d_in[9];
    const float* C_re     = (const float*)d_in[10];
    const float* C_im     = (const float*)d_in[11];
    const float* Dv       = (const float*)d_in[12];
    const float* Wout     = (const float*)d_in[13];
    const float* bout     = (const float*)d_in[14];
    const float* W1       = (const float*)d_in[15];
    const float* b1       = (const float*)d_in[16];
    const float* W2       = (const float*)d_in[17];
    const float* b2       = (const float*)d_in[18];
    const float* Wf       = (const float*)d_in[19];
    const float* bf       = (const float*)d_in[20];

    float* o1 = (float*)d_out;
    float* o2 = (float*)d_out + (size_t)BHL;

    k_tb<<<BB, 256>>>(t, Wt, bt);
    k_ssm<<<(HH*NS+255)/256, 256>>>(log_dt, logA_real, A_imag, C_re, C_im);
    k_ln<<<dim3(LL/256, BB), 256>>>(x, ln_g, ln_b);
    k_scan<<<(BB*HH)/SCAN_WPB, 32*SCAN_WPB>>>(Dv);
    k_stage1<<<dim3(LL/64, HH/128, BB), 256>>>(Wout, bout, x, feat, Wf, bf);
    k_stage2<<<dim3(LL/64, HH/128, BB), 256>>>(W1, b1, W2, b2, x, o1, o2);
}

// round 3
// speedup vs baseline: 1.1145x; 1.0951x over previous
#include <cuda_runtime.h>
#include <math.h>

#define BB 32
#define HH 256
#define LL 2048
#define NS 64
#define FF 32
#define BHL (BB*HH*LL)

typedef unsigned long long u64;

// ---------------- f32x2 helpers (sm_103a packed fp32) ----------------
__device__ __forceinline__ u64 pk2(float lo, float hi) {
    u64 r; asm("mov.b64 %0, {%1, %2};" : "=l"(r) : "f"(lo), "f"(hi)); return r;
}
__device__ __forceinline__ void up2(u64 v, float& a, float& b) {
    asm("mov.b64 {%0, %1}, %2;" : "=f"(a), "=f"(b) : "l"(v));
}
__device__ __forceinline__ u64 fma2(u64 a, u64 b, u64 c) {
    u64 d; asm("fma.rn.f32x2 %0, %1, %2, %3;" : "=l"(d) : "l"(a), "l"(b), "l"(c)); return d;
}
__device__ __forceinline__ u64 mul2(u64 a, u64 b) {
    u64 d; asm("mul.rn.f32x2 %0, %1, %2;" : "=l"(d) : "l"(a), "l"(b)); return d;
}

// gate = tanh(o)*sigmoid(o), via one __expf.
__device__ __forceinline__ float gatef(float o) {
    float u = __expf(fminf(-o, 25.f));
    float u2 = u * u;
    return (1.f - u2) / ((1.f + u2) * (1.f + u));
}

// ---------------- scratch (device globals) ----------------
__device__ float g_tb[BB*HH];
__device__ float g_wr[HH*NS], g_wi[HH*NS];
__device__ float g_c0r[HH*NS], g_c0i[HH*NS], g_c1r[HH*NS], g_c1i[HH*NS];
__device__ float g_z [BHL];   // LayerNorm output z; later holds gated activations
__device__ float g_yf[BHL];   // fwd scan output -> gelu(y) in place

// ---------------- t @ Wt^T + bt ----------------
__global__ void k_tb(const float* __restrict__ t, const float* __restrict__ Wt,
                     const float* __restrict__ bt)
{
    __shared__ float ts[HH];
    int b = blockIdx.x, h = threadIdx.x;
    ts[h] = t[b*HH + h];
    __syncthreads();
    float acc = bt[h];
    const float* wrow = Wt + (size_t)h*HH;
    #pragma unroll 8
    for (int k = 0; k < HH; k++) acc = fmaf(ts[k], wrow[k], acc);
    g_tb[b*HH + h] = acc;
}

// ---------------- SSM parameter prep ----------------
__global__ void k_ssm(const float* __restrict__ log_dt, const float* __restrict__ logA_real,
                      const float* __restrict__ A_imag, const float* __restrict__ C_re,
                      const float* __restrict__ C_im)
{
    int i = blockIdx.x*blockDim.x + threadIdx.x;
    if (i >= HH*NS) return;
    int h = i / NS;
    float dt = expf(log_dt[h]);
    float Ar = -expf(logA_real[i]);
    float Ai = A_imag[i];
    float dr = dt*Ar, di = dt*Ai;
    float er = expf(dr);
    float wr = er*cosf(di), wi = er*sinf(di);
    g_wr[i] = wr; g_wi[i] = wi;
    float Er = wr - 1.0f, Ei = wi;
    float inv = 1.0f/(Ar*Ar + Ai*Ai);
    float qr = (Er*Ar + Ei*Ai)*inv;
    float qi = (Ei*Ar - Er*Ai)*inv;
    {
        float cr = C_re[i], ci = C_im[i];
        g_c0r[i] = 2.0f*(cr*qr - ci*qi);
        g_c0i[i] = 2.0f*(cr*qi + ci*qr);
    }
    {
        float cr = C_re[HH*NS + i], ci = C_im[HH*NS + i];
        g_c1r[i] = 2.0f*(cr*qr - ci*qi);
        g_c1i[i] = 2.0f*(cr*qi + ci*qr);
    }
}

// ---------------- xin = x + tb ; LayerNorm over H -> z ----------------
__global__ void k_ln(const float* __restrict__ x, const float* __restrict__ ln_g,
                     const float* __restrict__ ln_b)
{
    __shared__ float tbs[HH], gs[HH], bs[HH];
    int b = blockIdx.y;
    int l = blockIdx.x*256 + threadIdx.x;
    tbs[threadIdx.x] = g_tb[b*HH + threadIdx.x];
    gs[threadIdx.x]  = ln_g[threadIdx.x];
    bs[threadIdx.x]  = ln_b[threadIdx.x];
    __syncthreads();
    const float* xb = x + (size_t)b*HH*LL + l;
    float s = 0.f, ss = 0.f;
    #pragma unroll 8
    for (int h = 0; h < HH; h++) {
        float v = xb[(size_t)h*LL] + tbs[h];
        s += v; ss = fmaf(v, v, ss);
    }
    float mu  = s * (1.0f/HH);
    float var = ss*(1.0f/HH) - mu*mu;
    float rstd = rsqrtf(var + 1e-5f);
    float* zb = g_z + (size_t)b*HH*LL + l;
    #pragma unroll 8
    for (int h = 0; h < HH; h++) {
        float v = xb[(size_t)h*LL] + tbs[h];
        zb[(size_t)h*LL] = (v - mu)*rstd*gs[h] + bs[h];
    }
}

// ---------------- bidirectional scan, f32x2 states, scalar-f32 transpose buffer ----------------
#define SCAN_WPB 4
__global__ __launch_bounds__(32*SCAN_WPB) void k_scan(const float* __restrict__ Dv)
{
    __shared__ __align__(16) float pbuf[SCAN_WPB][32*33];
    __shared__ __align__(16) u64   zbuf[SCAN_WPB][32];
    int wid  = threadIdx.x >> 5;
    int lane = threadIdx.x & 31;
    int bh   = blockIdx.x*SCAN_WPB + wid;
    int h    = bh & (HH-1);
    int ci   = h*NS + lane;
    float* pw = pbuf[wid];
    u64*   zw = zbuf[wid];

    u64 wr2  = pk2(g_wr[ci],  g_wr[ci+32]);
    u64 wi2  = pk2(g_wi[ci],  g_wi[ci+32]);
    u64 wi2n = pk2(-g_wi[ci], -g_wi[ci+32]);
    const float* zp = g_z  + (size_t)bh*LL;
    float*       yp = g_yf + (size_t)bh*LL;

    // ---- phase 1: forward scan ----
    {
        u64 cr2  = pk2(g_c0r[ci],  g_c0r[ci+32]);
        u64 ci2n = pk2(-g_c0i[ci], -g_c0i[ci+32]);
        u64 sr = 0ULL, si = 0ULL;
        for (int t = 0; t < LL/32; t++) {
            int l0 = t*32;
            float zv = zp[l0 + lane];
            zw[lane] = pk2(zv, zv);
            __syncwarp();
            #pragma unroll
            for (int j = 0; j < 32; j++) {
                u64 z2  = zw[j];
                u64 nsr = fma2(wr2, sr, fma2(wi2n, si, z2));
                si = fma2(wr2, si, mul2(wi2, sr));
                sr = nsr;
                u64 p2 = fma2(cr2, sr, mul2(ci2n, si));
                float pa, pb; up2(p2, pa, pb);
                pw[j*33 + lane] = pa + pb;
            }
            __syncwarp();
            float acc = 0.f;
            #pragma unroll
            for (int k = 0; k < 32; k++) acc += pw[lane*33 + k];
            yp[l0 + lane] = acc;
            __syncwarp();
        }
    }
    // ---- phase 2: backward scan + D*z + gelu (fused epilogue) ----
    {
        u64 cr2  = pk2(g_c1r[ci],  g_c1r[ci+32]);
        u64 ci2n = pk2(-g_c1i[ci], -g_c1i[ci+32]);
        float d = Dv[h];
        u64 sr = 0ULL, si = 0ULL;
        for (int t = 0; t < LL/32; t++) {
            int l0 = LL - 32*(t+1);
            float zv = zp[l0 + lane];
            zw[lane] = pk2(zv, zv);
            __syncwarp();
            #pragma unroll
            for (int j = 31; j >= 0; j--) {
                // emit y_b contribution from state BEFORE absorbing z[l0+j]
                u64 p2 = fma2(cr2, sr, mul2(ci2n, si));
                float pa, pb; up2(p2, pa, pb);
                pw[j*33 + lane] = pa + pb;
                u64 z2  = zw[j];
                u64 nsr = fma2(wr2, sr, fma2(wi2n, si, z2));
                si = fma2(wr2, si, mul2(wi2, sr));
                sr = nsr;
            }
            __syncwarp();
            float acc = 0.f;
            #pragma unroll
            for (int k = 0; k < 32; k++) acc += pw[lane*33 + k];
            float y = yp[l0 + lane] + acc + d*zv;
            // gelu (tanh approximation, matches jax default)
            float u = 0.7978845608028654f * fmaf(0.044715f*y, y*y, y);
            float e = __expf(fminf(-2.f*u, 80.f));
            float th = (1.f - e) / (1.f + e);
            yp[l0 + lane] = 0.5f*y*(1.f + th);
            __syncwarp();
        }
    }
}

// ---------------- stage1: (Wout GEMM + feature GEMM + residual + gate) -> g_z ----------------
__global__ __launch_bounds__(256) void k_stage1(const float* __restrict__ Wout, const float* __restrict__ bout,
                         const float* __restrict__ x, const float* __restrict__ feat,
                         const float* __restrict__ Wf, const float* __restrict__ bf)
{
    __shared__ __align__(16) float Ws[16][130];
    __shared__ __align__(16) float Bs[16][65];
    const int b  = blockIdx.z;
    const int g0 = blockIdx.y * 128;
    const int l0 = blockIdx.x * 64;
    const int tid = threadIdx.x;
    const int tx = tid & 15, ty = tid >> 4;
    const int arow = tid >> 1, akg = (tid & 1) * 8;
    const int brow = tid >> 4, bc0 = tid & 15;

    u64 acc[4][4];
    #pragma unroll
    for (int r = 0; r < 4; r++)
        #pragma unroll
        for (int j = 0; j < 4; j++) acc[r][j] = 0ULL;

    const float* act = g_yf + (size_t)b*HH*LL;
    for (int k0 = 0; k0 < HH; k0 += 16) {
        float4 w0 = *(const float4*)(Wout + (size_t)(g0+arow)*HH + k0 + akg);
        float4 w1 = *(const float4*)(Wout + (size_t)(g0+arow)*HH + k0 + akg + 4);
        Ws[akg+0][arow]=w0.x; Ws[akg+1][arow]=w0.y; Ws[akg+2][arow]=w0.z; Ws[akg+3][arow]=w0.w;
        Ws[akg+4][arow]=w1.x; Ws[akg+5][arow]=w1.y; Ws[akg+6][arow]=w1.z; Ws[akg+7][arow]=w1.w;
        #pragma unroll
        for (int c = 0; c < 4; c++)
            Bs[brow][bc0 + 16*c] = act[(size_t)(k0+brow)*LL + l0 + bc0 + 16*c];
        __syncthreads();
        #pragma unroll
        for (int k = 0; k < 16; k++) {
            u64 ap[4], bp[4];
            #pragma unroll
            for (int r = 0; r < 4; r++) ap[r] = *(const u64*)&Ws[k][ty*8 + 2*r];
            #pragma unroll
            for (int j = 0; j < 4; j++) { float v = Bs[k][16*j + tx]; bp[j] = pk2(v, v); }
            #pragma unroll
            for (int r = 0; r < 4; r++)
                #pragma unroll
                for (int j = 0; j < 4; j++)
                    acc[r][j] = fma2(ap[r], bp[j], acc[r][j]);
        }
        __syncthreads();
    }
    const float* fb = feat + (size_t)b*FF*LL;
    for (int k0 = 0; k0 < FF; k0 += 16) {
        float4 w0 = *(const float4*)(Wf + (size_t)(g0+arow)*FF + k0 + akg);
        float4 w1 = *(const float4*)(Wf + (size_t)(g0+arow)*FF + k0 + akg + 4);
        Ws[akg+0][arow]=w0.x; Ws[akg+1][arow]=w0.y; Ws[akg+2][arow]=w0.z; Ws[akg+3][arow]=w0.w;
        Ws[akg+4][arow]=w1.x; Ws[akg+5][arow]=w1.y; Ws[akg+6][arow]=w1.z; Ws[akg+7][arow]=w1.w;
        #pragma unroll
        for (int c = 0; c < 4; c++)
            Bs[brow][bc0 + 16*c] = fb[(size_t)(k0+brow)*LL + l0 + bc0 + 16*c];
        __syncthreads();
        #pragma unroll
        for (int k = 0; k < 16; k++) {
            u64 ap[4], bp[4];
            #pragma unroll
            for (int r = 0; r < 4; r++) ap[r] = *(const u64*)&Ws[k][ty*8 + 2*r];
            #pragma unroll
            for (int j = 0; j < 4; j++) { float v = Bs[k][16*j + tx]; bp[j] = pk2(v, v); }
            #pragma unroll
            for (int r = 0; r < 4; r++)
                #pragma unroll
                for (int j = 0; j < 4; j++)
                    acc[r][j] = fma2(ap[r], bp[j], acc[r][j]);
        }
        __syncthreads();
    }
    float base[8];
    #pragma unroll
    for (int i = 0; i < 8; i++) {
        int g = g0 + ty*8 + i;
        base[i] = bout[g] + bf[g] + g_tb[b*HH + g];
    }
    #pragma unroll
    for (int r = 0; r < 4; r++) {
        int g = g0 + ty*8 + 2*r;
        #pragma unroll
        for (int j = 0; j < 4; j++) {
            float v0, v1; up2(acc[r][j], v0, v1);
            int col = l0 + 16*j + tx;
            size_t off0 = ((size_t)b*HH + g)*LL + col;
            size_t off1 = off0 + LL;
            float o0 = v0 + base[2*r]   + x[off0];
            float o1 = v1 + base[2*r+1] + x[off1];
            g_z[off0] = gatef(o0);
            g_z[off1] = gatef(o1);
        }
    }
}

// ---------------- stage2: o1 = W1@g + b1 + x ; o2 = W2@g + b2 ----------------
__global__ __launch_bounds__(256) void k_stage2(const float* __restrict__ W1, const float* __restrict__ b1,
                         const float* __restrict__ W2, const float* __restrict__ b2,
                         const float* __restrict__ x, float* __restrict__ o1,
                         float* __restrict__ o2)
{
    __shared__ __align__(16) float W1s[16][130];
    __shared__ __align__(16) float W2s[16][130];
    __shared__ __align__(16) float Bs[16][65];
    const int b  = blockIdx.z;
    const int g0 = blockIdx.y * 128;
    const int l0 = blockIdx.x * 64;
    const int tid = threadIdx.x;
    const int tx = tid & 15, ty = tid >> 4;
    const int arow = tid >> 1, akg = (tid & 1) * 8;
    const int brow = tid >> 4, bc0 = tid & 15;

    u64 acc1[4][4], acc2[4][4];
    #pragma unroll
    for (int r = 0; r < 4; r++)
        #pragma unroll
        for (int j = 0; j < 4; j++) { acc1[r][j] = 0ULL; acc2[r][j] = 0ULL; }

    const float* gb = g_z + (size_t)b*HH*LL;
    for (int k0 = 0; k0 < HH; k0 += 16) {
        float4 w0 = *(const float4*)(W1 + (size_t)(g0+arow)*HH + k0 + akg);
        float4 w1 = *(const float4*)(W1 + (size_t)(g0+arow)*HH + k0 + akg + 4);
        W1s[akg+0][arow]=w0.x; W1s[akg+1][arow]=w0.y; W1s[akg+2][arow]=w0.z; W1s[akg+3][arow]=w0.w;
        W1s[akg+4][arow]=w1.x; W1s[akg+5][arow]=w1.y; W1s[akg+6][arow]=w1.z; W1s[akg+7][arow]=w1.w;
        float4 v0 = *(const float4*)(W2 + (size_t)(g0+arow)*HH + k0 + akg);
        float4 v1 = *(const float4*)(W2 + (size_t)(g0+arow)*HH + k0 + akg + 4);
        W2s[akg+0][arow]=v0.x; W2s[akg+1][arow]=v0.y; W2s[akg+2][arow]=v0.z; W2s[akg+3][arow]=v0.w;
        W2s[akg+4][arow]=v1.x; W2s[akg+5][arow]=v1.y; W2s[akg+6][arow]=v1.z; W2s[akg+7][arow]=v1.w;
        #pragma unroll
        for (int c = 0; c < 4; c++)
            Bs[brow][bc0 + 16*c] = gb[(size_t)(k0+brow)*LL + l0 + bc0 + 16*c];
        __syncthreads();
        #pragma unroll
        for (int k = 0; k < 16; k++) {
            u64 a1[4], a2[4], bp[4];
            #pragma unroll
            for (int r = 0; r < 4; r++) a1[r] = *(const u64*)&W1s[k][ty*8 + 2*r];
            #pragma unroll
            for (int r = 0; r < 4; r++) a2[r] = *(const u64*)&W2s[k][ty*8 + 2*r];
            #pragma unroll
            for (int j = 0; j < 4; j++) { float v = Bs[k][16*j + tx]; bp[j] = pk2(v, v); }
            #pragma unroll
            for (int r = 0; r < 4; r++)
                #pragma unroll
                for (int j = 0; j < 4; j++) {
                    acc1[r][j] = fma2(a1[r], bp[j], acc1[r][j]);
                    acc2[r][j] = fma2(a2[r], bp[j], acc2[r][j]);
                }
        }
        __syncthreads();
    }
    #pragma unroll
    for (int r = 0; r < 4; r++) {
        int g = g0 + ty*8 + 2*r;
        float bb1a = b1[g], bb1b = b1[g+1];
        float bb2a = b2[g], bb2b = b2[g+1];
        #pragma unroll
        for (int j = 0; j < 4; j++) {
            int col = l0 + 16*j + tx;
            size_t off0 = ((size_t)b*HH + g)*LL + col;
            size_t off1 = off0 + LL;
            float p0, p1, q0, q1;
            up2(acc1[r][j], p0, p1);
            up2(acc2[r][j], q0, q1);
            o1[off0] = p0 + bb1a + x[off0];
            o1[off1] = p1 + bb1b + x[off1];
            o2[off0] = q0 + bb2a;
            o2[off1] = q1 + bb2b;
        }
    }
}

// ---------------- launch ----------------
extern "C" void kernel_launch(void* const* d_in, const int* in_sizes, int n_in,
                              void* d_out, int out_size)
{
    const float* x        = (const float*)d_in[0];
    const float* t        = (const float*)d_in[1];
    const float* feat     = (const float*)d_in[2];
    const float* Wt       = (const float*)d_in[3];
    const float* bt       = (const float*)d_in[4];
    const float* ln_g     = (const float*)d_in[5];
    const float* ln_b     = (const float*)d_in[6];
    const float* log_dt   = (const float*)d_in[7];
    const float* logA_real= (const float*)d_in[8];
    const float* A_imag   = (const float*)d_in[9];
    const float* C_re     = (const float*)d_in[10];
    const float* C_im     = (const float*)d_in[11];
    const float* Dv       = (const float*)d_in[12];
    const float* Wout     = (const float*)d_in[13];
    const float* bout     = (const float*)d_in[14];
    const float* W1       = (const float*)d_in[15];
    const float* b1       = (const float*)d_in[16];
    const float* W2       = (const float*)d_in[17];
    const float* b2       = (const float*)d_in[18];
    const float* Wf       = (const float*)d_in[19];
    const float* bf       = (const float*)d_in[20];

    float* o1 = (float*)d_out;
    float* o2 = (float*)d_out + (size_t)BHL;

    k_tb<<<BB, 256>>>(t, Wt, bt);
    k_ssm<<<(HH*NS+255)/256, 256>>>(log_dt, logA_real, A_imag, C_re, C_im);
    k_ln<<<dim3(LL/256, BB), 256>>>(x, ln_g, ln_b);
    k_scan<<<(BB*HH)/SCAN_WPB, 32*SCAN_WPB>>>(Dv);
    k_stage1<<<dim3(LL/64, HH/128, BB), 256>>>(Wout, bout, x, feat, Wf, bf);
    k_stage2<<<dim3(LL/64, HH/128, BB), 256>>>(W1, b1, W2, b2, x, o1, o2);
}